// round 12
// baseline (speedup 1.0000x reference)
#include <cuda_runtime.h>
#include <cuda_bf16.h>
#include <math.h>
#include <stdint.h>

#define N_BATCH 4096
#define V_N     26
#define C_N     256
#define K_N     3
#define NV      (N_BATCH * V_N)            /* 106496 */
#define TS      25

/* ------------------------------------------------------------------ */
/* Device scratch (no cudaMalloc allowed)                              */
/* ------------------------------------------------------------------ */
__device__ float g_HA[(size_t)NV * C_N];        /* hidden fp32 ping    */
__device__ float g_HB[(size_t)NV * C_N];        /* hidden fp32 pong    */
__device__ float g_Y [(size_t)NV * 3 * C_N];    /* conv out fp32       */
__device__ float g_G [(size_t)NV * 3 * C_N];    /* gate pre-act fp32   */
__device__ float g_P [4][(size_t)NV * 3];       /* pred history ring   */
__device__ float g_part[2][(size_t)NV * 3];     /* W3 partials         */
__device__ __align__(16) float g_Aadj[K_N * V_N * 28];

/* bf16 hi/lo split activation buffers */
__device__ __nv_bfloat16 g_HAh[(size_t)NV * C_N], g_HAl[(size_t)NV * C_N];
__device__ __nv_bfloat16 g_HBh[(size_t)NV * C_N], g_HBl[(size_t)NV * C_N];
__device__ __nv_bfloat16 g_Mh [(size_t)NV * C_N], g_Ml [(size_t)NV * C_N];
__device__ __nv_bfloat16 g_D1h[(size_t)NV * C_N], g_D1l[(size_t)NV * C_N];

/* bf16 hi/lo split weights */
__device__ __nv_bfloat16 g_cwH[768 * 256], g_cwL[768 * 256];
__device__ __nv_bfloat16 g_WhH[768 * 256], g_WhL[768 * 256];
__device__ __nv_bfloat16 g_W1H[256 * 256], g_W1L[256 * 256];
__device__ __nv_bfloat16 g_W2H[256 * 256], g_W2L[256 * 256];

/* ------------------------------------------------------------------ */
/* JAX threefry2x32 noise (partitionable path; verified R4)            */
/* ------------------------------------------------------------------ */
__device__ __forceinline__ uint32_t rotl32(uint32_t x, uint32_t r) {
    return (x << r) | (x >> (32u - r));
}

__device__ __forceinline__ float jax_noise(int s, int r, int d)
{
    uint32_t idx = (uint32_t)((s * NV + r) * 3 + d);
    uint32_t x0 = 0u, x1 = idx;
    const uint32_t K0 = 0u, K1 = 1u, K2 = 0x1BD11BDBu;
    x0 += K0; x1 += K1;
#define QR(rv) { x0 += x1; x1 = rotl32(x1, rv); x1 ^= x0; }
    QR(13) QR(15) QR(26) QR(6)
    x0 += K1; x1 += K2 + 1u;
    QR(17) QR(29) QR(16) QR(24)
    x0 += K2; x1 += K0 + 2u;
    QR(13) QR(15) QR(26) QR(6)
    x0 += K0; x1 += K1 + 3u;
    QR(17) QR(29) QR(16) QR(24)
    x0 += K1; x1 += K2 + 4u;
    QR(13) QR(15) QR(26) QR(6)
    x0 += K2; x1 += K0 + 5u;
#undef QR
    uint32_t bits = x0 ^ x1;
    float f = __uint_as_float((bits >> 9) | 0x3f800000u) - 1.0f;
    const float lo = -0.99999994f;
    float u = fmaxf(lo, f * 2.0f + lo);
    return (1.41421354f * erfinvf(u)) * 5e-4f;
}

/* ------------------------------------------------------------------ */
/* helpers                                                             */
/* ------------------------------------------------------------------ */
__device__ __forceinline__ uint32_t smem_u32(const void* p) {
    uint32_t a;
    asm("{ .reg .u64 t; cvta.to.shared.u64 t, %1; cvt.u32.u64 %0, t; }"
        : "=r"(a) : "l"(p));
    return a;
}

__device__ __forceinline__ void ldsm4(uint32_t* d, uint32_t addr) {
    asm volatile("ldmatrix.sync.aligned.m8n8.x4.shared.b16 {%0,%1,%2,%3}, [%4];"
                 : "=r"(d[0]), "=r"(d[1]), "=r"(d[2]), "=r"(d[3]) : "r"(addr));
}

__device__ __forceinline__ void mma_bf16(float* c, const uint32_t* a, const uint32_t* b) {
    asm volatile("mma.sync.aligned.m16n8k16.row.col.f32.bf16.bf16.f32 "
                 "{%0,%1,%2,%3}, {%4,%5,%6,%7}, {%8,%9}, {%0,%1,%2,%3};"
                 : "+f"(c[0]), "+f"(c[1]), "+f"(c[2]), "+f"(c[3])
                 : "r"(a[0]), "r"(a[1]), "r"(a[2]), "r"(a[3]),
                   "r"(b[0]), "r"(b[1]));
}

#define CP16(dst, src) \
    asm volatile("cp.async.cg.shared.global [%0], [%1], 16;" \
                 :: "r"(dst), "l"(src) : "memory")
#define CP_COMMIT() asm volatile("cp.async.commit_group;" ::: "memory")
#define CP_WAIT(n)  asm volatile("cp.async.wait_group %0;" :: "n"(n) : "memory")

__device__ __forceinline__ void split1(float x, __nv_bfloat16& h, __nv_bfloat16& l) {
    h = __float2bfloat16(x);
    l = __float2bfloat16(x - __bfloat162float(h));
}

/* ------------------------------------------------------------------ */
/* GEMM via mma.sync bf16-split, cp.async double-buffered.             */
/* C[M,Nout] = (Ah+Al)[M,256] @ (Bh+Bl)[Nout,256]^T  (3-product)       */
/* grid (Nout/128, M/128), 256 thr, 8 warps 4m x 2n, warp tile 32x64.  */
/* epi: 0 none | 1 +bias | 2 +bias+leaky (store Cf and/or Ch/Cl)       */
/*      3 +bias+leaky then W3 partial reduction (no C store)           */
/* ------------------------------------------------------------------ */
#define STR   40                              /* smem row stride (bf16) */
#define ARRB  (128 * STR * 2)                 /* bytes per tile: 10240  */
#define STAGEB (4 * ARRB)                     /* bytes per stage: 40960 */
#define GEMM_SMEM (2 * STAGEB)                /* 81920                  */

__global__ void __launch_bounds__(256, 2)
gemm_mma(const __nv_bfloat16* __restrict__ Ah, const __nv_bfloat16* __restrict__ Al,
         const __nv_bfloat16* __restrict__ Bh, const __nv_bfloat16* __restrict__ Bl,
         float* __restrict__ Cf,
         __nv_bfloat16* __restrict__ Ch, __nv_bfloat16* __restrict__ Cl,
         int Nout, const float* __restrict__ bias, int epi,
         const float* __restrict__ W3g, float* __restrict__ part)
{
    extern __shared__ __align__(16) char sm[];
    __shared__ float sW3[768];
    __shared__ float outacc[128][2][3];
    const uint32_t sb = smem_u32(sm);

    const int tid  = threadIdx.x;
    const int lane = tid & 31, w = tid >> 5;
    const int wm = w >> 1, wn = w & 1;
    const int m0 = blockIdx.y * 128, n0 = blockIdx.x * 128;

    if (epi == 3)
        for (int i = tid; i < 768; i += 256) sW3[i] = W3g[i];

    float acc[2][8][4];
#pragma unroll
    for (int i = 0; i < 2; i++)
#pragma unroll
        for (int j = 0; j < 8; j++)
#pragma unroll
            for (int q = 0; q < 4; q++) acc[i][j][q] = 0.f;

    const int lrow = tid >> 1;
    const int lcol = (tid & 1) * 16;
    const size_t aoff = (size_t)(m0 + lrow) * 256 + lcol;
    const size_t boff = (size_t)(n0 + lrow) * 256 + lcol;
    const __nv_bfloat16* src[4] = { Ah + aoff, Al + aoff, Bh + boff, Bl + boff };
    const uint32_t dbase = sb + (uint32_t)(lrow * STR + lcol) * 2u;

    auto load_stage = [&](int kc, int st) {
#pragma unroll
        for (int a = 0; a < 4; a++) {
            const __nv_bfloat16* s = src[a] + kc * 32;
            uint32_t d = dbase + st * STAGEB + a * ARRB;
            CP16(d,      s);
            CP16(d + 16, s + 8);
        }
        CP_COMMIT();
    };

    load_stage(0, 0);

    for (int kc = 0; kc < 8; kc++) {
        if (kc < 7) load_stage(kc + 1, (kc + 1) & 1);
        if (kc < 7) { CP_WAIT(1); } else { CP_WAIT(0); }
        __syncthreads();

        const uint32_t sbase = sb + (kc & 1) * STAGEB;
#pragma unroll
        for (int ks = 0; ks < 2; ks++) {
            uint32_t ah[2][4], alr[2][4];
#pragma unroll
            for (int mt = 0; mt < 2; mt++) {
                uint32_t r = (uint32_t)(wm * 32 + mt * 16 + (lane & 15));
                uint32_t c = (uint32_t)(ks * 16 + (lane >> 4) * 8);
                uint32_t off = sbase + (r * STR + c) * 2;
                ldsm4(ah[mt],  off);
                ldsm4(alr[mt], off + ARRB);
            }
#pragma unroll
            for (int pp = 0; pp < 2; pp++) {
                uint32_t bh[2][4], bl[2][4];
#pragma unroll
                for (int pi = 0; pi < 2; pi++) {
                    const int p = pp * 2 + pi;
                    uint32_t g = lane >> 3, rr = lane & 7;
                    uint32_t r = (uint32_t)(wn * 64 + p * 16 + ((g & 2) ? 8 : 0) + rr);
                    uint32_t c = (uint32_t)(ks * 16 + ((g & 1) ? 8 : 0));
                    uint32_t off = sbase + 2 * ARRB + (r * STR + c) * 2;
                    ldsm4(bh[pi], off);
                    ldsm4(bl[pi], off + ARRB);
                }
#pragma unroll
                for (int pi = 0; pi < 2; pi++)
#pragma unroll
                    for (int mt = 0; mt < 2; mt++)
#pragma unroll
                        for (int q = 0; q < 2; q++)
                            mma_bf16(acc[mt][(pp * 2 + pi) * 2 + q],
                                     ah[mt], &bh[pi][q * 2]);
#pragma unroll
                for (int pi = 0; pi < 2; pi++)
#pragma unroll
                    for (int mt = 0; mt < 2; mt++)
#pragma unroll
                        for (int q = 0; q < 2; q++)
                            mma_bf16(acc[mt][(pp * 2 + pi) * 2 + q],
                                     ah[mt], &bl[pi][q * 2]);
#pragma unroll
                for (int pi = 0; pi < 2; pi++)
#pragma unroll
                    for (int mt = 0; mt < 2; mt++)
#pragma unroll
                        for (int q = 0; q < 2; q++)
                            mma_bf16(acc[mt][(pp * 2 + pi) * 2 + q],
                                     alr[mt], &bh[pi][q * 2]);
            }
        }
        __syncthreads();
    }

    if (epi == 3) {
        /* bias + leaky + W3 partial reduction; D2 never materialized */
        float prt[2][2][3];
#pragma unroll
        for (int mt = 0; mt < 2; mt++)
#pragma unroll
            for (int h = 0; h < 2; h++)
#pragma unroll
                for (int d = 0; d < 3; d++) prt[mt][h][d] = 0.f;

#pragma unroll
        for (int nt = 0; nt < 8; nt++) {
            const int cg = n0 + wn * 64 + nt * 8 + (lane & 3) * 2;
            const float bb0 = bias[cg], bb1 = bias[cg + 1];
#pragma unroll
            for (int mt = 0; mt < 2; mt++)
#pragma unroll
                for (int h = 0; h < 2; h++) {
                    float v0 = acc[mt][nt][h * 2 + 0] + bb0;
                    float v1 = acc[mt][nt][h * 2 + 1] + bb1;
                    v0 = v0 > 0.f ? v0 : 0.1f * v0;
                    v1 = v1 > 0.f ? v1 : 0.1f * v1;
#pragma unroll
                    for (int d = 0; d < 3; d++)
                        prt[mt][h][d] += v0 * sW3[d * 256 + cg]
                                       + v1 * sW3[d * 256 + cg + 1];
                }
        }
#pragma unroll
        for (int mt = 0; mt < 2; mt++)
#pragma unroll
            for (int h = 0; h < 2; h++)
#pragma unroll
                for (int d = 0; d < 3; d++) {
                    float v = prt[mt][h][d];
                    v += __shfl_xor_sync(0xffffffffu, v, 1);
                    v += __shfl_xor_sync(0xffffffffu, v, 2);
                    if ((lane & 3) == 0)
                        outacc[wm * 32 + mt * 16 + h * 8 + (lane >> 2)][wn][d] = v;
                }
        __syncthreads();
        if (tid < 128) {
            float* dst = part + (size_t)blockIdx.x * NV * 3 + (size_t)(m0 + tid) * 3;
#pragma unroll
            for (int d = 0; d < 3; d++)
                dst[d] = outacc[tid][0][d] + outacc[tid][1][d];
        }
        return;
    }

    /* epilogue: stores */
#pragma unroll
    for (int mt = 0; mt < 2; mt++) {
        const int r0 = m0 + wm * 32 + mt * 16 + (lane >> 2);
#pragma unroll
        for (int nt = 0; nt < 8; nt++) {
            const int c0 = n0 + wn * 64 + nt * 8 + (lane & 3) * 2;
            float b0 = 0.f, b1 = 0.f;
            if (bias) { b0 = bias[c0]; b1 = bias[c0 + 1]; }
#pragma unroll
            for (int h = 0; h < 2; h++) {
                const int r = r0 + h * 8;
                float v0 = acc[mt][nt][h * 2 + 0] + b0;
                float v1 = acc[mt][nt][h * 2 + 1] + b1;
                if (epi == 2) {
                    v0 = v0 > 0.f ? v0 : 0.1f * v0;
                    v1 = v1 > 0.f ? v1 : 0.1f * v1;
                }
                const size_t o = (size_t)r * Nout + c0;
                if (Cf) *(float2*)(Cf + o) = make_float2(v0, v1);
                if (Ch) {
                    __nv_bfloat16 h0, l0, h1, l1;
                    split1(v0, h0, l0);
                    split1(v1, h1, l1);
                    *(uint32_t*)(Ch + o) =
                        ((uint32_t)__bfloat16_as_ushort(h1) << 16) | __bfloat16_as_ushort(h0);
                    *(uint32_t*)(Cl + o) =
                        ((uint32_t)__bfloat16_as_ushort(l1) << 16) | __bfloat16_as_ushort(l0);
                }
            }
        }
    }
}

/* ------------------------------------------------------------------ */
/* Graph mix: M[(n,w),c] = sum_{k,v} Y[(n,v),k*256+c] * Aadj[k,v,w]    */
/* ------------------------------------------------------------------ */
__global__ void __launch_bounds__(256)
graphmix_kernel(const float* __restrict__ Y,
                __nv_bfloat16* __restrict__ Mh, __nv_bfloat16* __restrict__ Ml)
{
    __shared__ __align__(16) float sA[K_N * V_N * 28];
    const int n = blockIdx.x;
    const int tid = threadIdx.x;
    for (int i = tid; i < K_N * V_N * 28; i += 256) sA[i] = g_Aadj[i];
    __syncthreads();

    const float* Yn = Y + (size_t)n * V_N * 768;
    const int c = tid;
    float acc[28];
#pragma unroll
    for (int w = 0; w < 28; w++) acc[w] = 0.f;

#pragma unroll
    for (int k = 0; k < K_N; k++) {
#pragma unroll
        for (int v = 0; v < V_N; v++) {
            float yv = Yn[v * 768 + k * 256 + c];
            const float4* arow = (const float4*)&sA[(k * V_N + v) * 28];
#pragma unroll
            for (int q = 0; q < 7; q++) {
                float4 a4 = arow[q];
                acc[q * 4 + 0] += yv * a4.x;
                acc[q * 4 + 1] += yv * a4.y;
                acc[q * 4 + 2] += yv * a4.z;
                acc[q * 4 + 3] += yv * a4.w;
            }
        }
    }
    for (int w = 0; w < V_N; w++) {
        __nv_bfloat16 h, l;
        split1(acc[w], h, l);
        const size_t o = ((size_t)n * V_N + w) * 256 + c;
        Mh[o] = h;
        Ml[o] = l;
    }
}

/* ------------------------------------------------------------------ */
/* GRU elementwise (thin: one block per row — proven fastest in R8)    */
/* ------------------------------------------------------------------ */
__global__ void __launch_bounds__(256)
gru_kernel(const float* __restrict__ H, const float* __restrict__ G,
           const float* __restrict__ P1, const float* __restrict__ P2,
           const float* __restrict__ P3,
           const float* __restrict__ Wir, const float* __restrict__ bir,
           const float* __restrict__ Wii, const float* __restrict__ bii,
           const float* __restrict__ Win, const float* __restrict__ bin,
           float* __restrict__ Hnew,
           __nv_bfloat16* __restrict__ Hh, __nv_bfloat16* __restrict__ Hl,
           int s)
{
    const int r = blockIdx.x;
    const int c = threadIdx.x;
    __shared__ float sx[9];
    if (c < 3) {
        float h1 = P1[r * 3 + c], h2 = P2[r * 3 + c], h3 = P3[r * 3 + c];
        float nz = jax_noise(s, r, c);
        float insv = h2 - h3;
        sx[c]     = h1 + nz;
        sx[3 + c] = insv;
        sx[6 + c] = (h1 - h2) - insv;
    }
    __syncthreads();

    float xr = bir[c], xi = bii[c], xn = bin[c];
#pragma unroll
    for (int d = 0; d < 9; d++) {
        float xv = sx[d];
        xr += xv * Wir[c * 9 + d];
        xi += xv * Wii[c * 9 + d];
        xn += xv * Win[c * 9 + d];
    }
    size_t g = (size_t)r * 768;
    float gr = G[g + c], gi = G[g + 256 + c], gh = G[g + 512 + c];
    float rg = 1.f / (1.f + expf(-(xr + gr)));
    float zg = 1.f / (1.f + expf(-(xi + gi)));
    float nn = tanhf(xn + rg * gh);
    float hp = H[(size_t)r * 256 + c];
    float hv = (1.f - zg) * nn + zg * hp;
    const size_t o = (size_t)r * 256 + c;
    Hnew[o] = hv;
    __nv_bfloat16 hh, hl;
    split1(hv, hh, hl);
    Hh[o] = hh;
    Hl[o] = hl;
}

/* ------------------------------------------------------------------ */
/* Combine W3 partials: pred = P1 + noise + (part0 + part1 + b3)       */
/* ------------------------------------------------------------------ */
__global__ void __launch_bounds__(256)
out_combine(const float* __restrict__ part,
            const float* __restrict__ b3, const float* __restrict__ P1,
            float* __restrict__ Pnew, float* __restrict__ out, int s)
{
    const int r = blockIdx.x * 256 + threadIdx.x;
#pragma unroll
    for (int d = 0; d < 3; d++) {
        float res = part[(size_t)r * 3 + d]
                  + part[(size_t)NV * 3 + (size_t)r * 3 + d] + b3[d];
        float p = (P1[r * 3 + d] + jax_noise(s, r, d)) + res;
        Pnew[r * 3 + d] = p;
        out[((size_t)r * TS + s) * 3 + d] = p;
    }
}

/* ------------------------------------------------------------------ */
/* Prep kernels                                                        */
/* ------------------------------------------------------------------ */
__global__ void prep_aadj(const float* __restrict__ A,
                          const float* __restrict__ em,
                          const float* __restrict__ ea)
{
    int i = blockIdx.x * 256 + threadIdx.x;
    if (i >= K_N * V_N * 28) return;
    int w = i % 28, kv = i / 28;
    g_Aadj[i] = (w < V_N) ? (A[kv * V_N + w] * em[kv * V_N + w] + ea[kv * V_N + w])
                          : 0.f;
}

__global__ void split_weights(const float* __restrict__ conv_w,
                              const float* __restrict__ Whr,
                              const float* __restrict__ Whi,
                              const float* __restrict__ Whh,
                              const float* __restrict__ W1,
                              const float* __restrict__ W2)
{
    int i = blockIdx.x * 256 + threadIdx.x;  /* 524288 total */
    const float* src;
    __nv_bfloat16 *dh, *dl;
    int off;
    if (i < 196608)       { src = conv_w; dh = g_cwH; dl = g_cwL; off = i; }
    else if (i < 262144)  { src = Whr; dh = g_WhH; dl = g_WhL; off = i - 196608; }
    else if (i < 327680)  { src = Whi; dh = g_WhH + 65536; dl = g_WhL + 65536; off = i - 262144; }
    else if (i < 393216)  { src = Whh; dh = g_WhH + 131072; dl = g_WhL + 131072; off = i - 327680; }
    else if (i < 458752)  { src = W1; dh = g_W1H; dl = g_W1L; off = i - 393216; }
    else                  { src = W2; dh = g_W2H; dl = g_W2L; off = i - 458752; }
    __nv_bfloat16 h, l;
    split1(src[off], h, l);
    dh[off] = h;
    dl[off] = l;
}

/* hidden [N,C,V] -> H [(n,v),c] fp32 + split, one block per n */
__global__ void __launch_bounds__(256)
transpose_h(const float* __restrict__ hid, float* __restrict__ H,
            __nv_bfloat16* __restrict__ Hh, __nv_bfloat16* __restrict__ Hl)
{
    __shared__ float sm[C_N * V_N];
    const int n = blockIdx.x;
    const float* src = hid + (size_t)n * C_N * V_N;
    for (int i = threadIdx.x; i < C_N * V_N; i += 256) sm[i] = src[i];
    __syncthreads();
    const size_t base = (size_t)n * V_N * C_N;
    for (int i = threadIdx.x; i < C_N * V_N; i += 256) {
        int v = i >> 8, c = i & 255;
        float x = sm[c * V_N + v];
        H[base + i] = x;
        __nv_bfloat16 hh, ll;
        split1(x, hh, ll);
        Hh[base + i] = hh;
        Hl[base + i] = ll;
    }
}

/* ------------------------------------------------------------------ */
/* Host driver                                                         */
/* ------------------------------------------------------------------ */
extern "C" void kernel_launch(void* const* d_in, const int* in_sizes, int n_in,
                              void* d_out, int out_size)
{
    const float* in0    = (const float*)d_in[0];
    const float* in1    = (const float*)d_in[1];
    const float* in2    = (const float*)d_in[2];
    const float* hidden = (const float*)d_in[3];
    const float* A      = (const float*)d_in[4];
    const float* emul   = (const float*)d_in[5];
    const float* eadd   = (const float*)d_in[6];
    const float* conv_w = (const float*)d_in[7];
    const float* conv_b = (const float*)d_in[8];
    const float* Wir    = (const float*)d_in[9];
    const float* bir    = (const float*)d_in[10];
    const float* Wii    = (const float*)d_in[11];
    const float* bii    = (const float*)d_in[12];
    const float* Win    = (const float*)d_in[13];
    const float* b_in   = (const float*)d_in[14];
    const float* Whr    = (const float*)d_in[15];
    const float* Whi    = (const float*)d_in[16];
    const float* Whh    = (const float*)d_in[17];
    const float* W1     = (const float*)d_in[18];
    const float* b1     = (const float*)d_in[19];
    const float* W2     = (const float*)d_in[20];
    const float* b2     = (const float*)d_in[21];
    const float* W3     = (const float*)d_in[22];
    const float* b3     = (const float*)d_in[23];
    float* out = (float*)d_out;

    float *pHA, *pHB, *pY, *pG, *pPbase, *pPart;
    cudaGetSymbolAddress((void**)&pHA, g_HA);
    cudaGetSymbolAddress((void**)&pHB, g_HB);
    cudaGetSymbolAddress((void**)&pY,  g_Y);
    cudaGetSymbolAddress((void**)&pG,  g_G);
    cudaGetSymbolAddress((void**)&pPbase, g_P);
    cudaGetSymbolAddress((void**)&pPart,  g_part);

    __nv_bfloat16 *pHAh, *pHAl, *pHBh, *pHBl, *pMh, *pMl, *pD1h, *pD1l;
    __nv_bfloat16 *pcwH, *pcwL, *pWhH, *pWhL, *pW1H, *pW1L, *pW2H, *pW2L;
    cudaGetSymbolAddress((void**)&pHAh, g_HAh);
    cudaGetSymbolAddress((void**)&pHAl, g_HAl);
    cudaGetSymbolAddress((void**)&pHBh, g_HBh);
    cudaGetSymbolAddress((void**)&pHBl, g_HBl);
    cudaGetSymbolAddress((void**)&pMh,  g_Mh);
    cudaGetSymbolAddress((void**)&pMl,  g_Ml);
    cudaGetSymbolAddress((void**)&pD1h, g_D1h);
    cudaGetSymbolAddress((void**)&pD1l, g_D1l);
    cudaGetSymbolAddress((void**)&pcwH, g_cwH);
    cudaGetSymbolAddress((void**)&pcwL, g_cwL);
    cudaGetSymbolAddress((void**)&pWhH, g_WhH);
    cudaGetSymbolAddress((void**)&pWhL, g_WhL);
    cudaGetSymbolAddress((void**)&pW1H, g_W1H);
    cudaGetSymbolAddress((void**)&pW1L, g_W1L);
    cudaGetSymbolAddress((void**)&pW2H, g_W2H);
    cudaGetSymbolAddress((void**)&pW2L, g_W2L);

    float* Pbuf[4];
    for (int i = 0; i < 4; i++) Pbuf[i] = pPbase + (size_t)i * NV * 3;

    cudaFuncSetAttribute(gemm_mma,
                         cudaFuncAttributeMaxDynamicSharedMemorySize, GEMM_SMEM);

    /* per-launch prep */
    prep_aadj<<<(K_N * V_N * 28 + 255) / 256, 256>>>(A, emul, eadd);
    transpose_h<<<N_BATCH, 256>>>(hidden, pHA, pHAh, pHAl);
    split_weights<<<524288 / 256, 256>>>(conv_w, Whr, Whi, Whh, W1, W2);
    cudaMemcpyAsync(Pbuf[0], in0, (size_t)NV * 3 * sizeof(float),
                    cudaMemcpyDeviceToDevice, 0);
    cudaMemcpyAsync(Pbuf[1], in1, (size_t)NV * 3 * sizeof(float),
                    cudaMemcpyDeviceToDevice, 0);
    cudaMemcpyAsync(Pbuf[2], in2, (size_t)NV * 3 * sizeof(float),
                    cudaMemcpyDeviceToDevice, 0);

    const dim3 grid768(6, NV / 128);
    const dim3 grid256(2, NV / 128);

    for (int s = 0; s < TS; s++) {
        float* Hcur  = (s & 1) ? pHB : pHA;
        float* Hnext = (s & 1) ? pHA : pHB;
        const __nv_bfloat16* Hch = (s & 1) ? pHBh : pHAh;
        const __nv_bfloat16* Hcl = (s & 1) ? pHBl : pHAl;
        __nv_bfloat16* Hnh = (s & 1) ? pHAh : pHBh;
        __nv_bfloat16* Hnl = (s & 1) ? pHAl : pHBl;

        const __nv_bfloat16 *GAh = Hch, *GAl = Hcl;
        if (s < 10) {
            gemm_mma<<<grid768, 256, GEMM_SMEM>>>(Hch, Hcl, pcwH, pcwL,
                                                  pY, nullptr, nullptr,
                                                  768, conv_b, 1, nullptr, nullptr);
            graphmix_kernel<<<N_BATCH, 256>>>(pY, pMh, pMl);
            GAh = pMh;
            GAl = pMl;
        }

        gemm_mma<<<grid768, 256, GEMM_SMEM>>>(GAh, GAl, pWhH, pWhL,
                                              pG, nullptr, nullptr,
                                              768, nullptr, 0, nullptr, nullptr);

        int m4 = s & 3;
        int i1   = (4 - m4) & 3;
        int i2   = (5 - m4) & 3;
        int i3   = (6 - m4) & 3;
        int inew = (7 - m4) & 3;

        gru_kernel<<<NV, 256>>>(Hcur, pG, Pbuf[i1], Pbuf[i2], Pbuf[i3],
                                Wir, bir, Wii, bii, Win, b_in,
                                Hnext, Hnh, Hnl, s);

        gemm_mma<<<grid256, 256, GEMM_SMEM>>>(Hnh, Hnl, pW1H, pW1L,
                                              nullptr, pD1h, pD1l,
                                              256, b1, 2, nullptr, nullptr);
        /* W2 GEMM with fused W3 projection: emits 3 partials/row */
        gemm_mma<<<grid256, 256, GEMM_SMEM>>>(pD1h, pD1l, pW2H, pW2L,
                                              nullptr, nullptr, nullptr,
                                              256, b2, 3, W3, pPart);

        out_combine<<<NV / 256, 256>>>(pPart, b3, Pbuf[i1], Pbuf[inew], out, s);
    }
}

// round 13
// speedup vs baseline: 1.0002x; 1.0002x over previous
#include <cuda_runtime.h>
#include <cuda_bf16.h>
#include <math.h>
#include <stdint.h>

#define N_BATCH 4096
#define V_N     26
#define C_N     256
#define K_N     3
#define NV      (N_BATCH * V_N)            /* 106496 */
#define TS      25

/* ------------------------------------------------------------------ */
/* Device scratch (no cudaMalloc allowed)                              */
/* ------------------------------------------------------------------ */
__device__ float g_HA[(size_t)NV * C_N];        /* hidden fp32 ping    */
__device__ float g_HB[(size_t)NV * C_N];        /* hidden fp32 pong    */
__device__ float g_Y [(size_t)NV * 3 * C_N];    /* conv out fp32       */
__device__ float g_G [(size_t)NV * 3 * C_N];    /* gate pre-act fp32   */
__device__ float g_P [4][(size_t)NV * 3];       /* pred history ring   */
__device__ float g_part[2][(size_t)NV * 3];     /* W3 partials         */
__device__ __align__(16) float g_Aadj[K_N * V_N * 28];

/* bf16 hi/lo split activation buffers */
__device__ __nv_bfloat16 g_HAh[(size_t)NV * C_N], g_HAl[(size_t)NV * C_N];
__device__ __nv_bfloat16 g_HBh[(size_t)NV * C_N], g_HBl[(size_t)NV * C_N];
__device__ __nv_bfloat16 g_Mh [(size_t)NV * C_N], g_Ml [(size_t)NV * C_N];
__device__ __nv_bfloat16 g_D1h[(size_t)NV * C_N], g_D1l[(size_t)NV * C_N];

/* bf16 hi/lo split weights */
__device__ __nv_bfloat16 g_cwH[768 * 256], g_cwL[768 * 256];
__device__ __nv_bfloat16 g_WhH[768 * 256], g_WhL[768 * 256];
__device__ __nv_bfloat16 g_W1H[256 * 256], g_W1L[256 * 256];
__device__ __nv_bfloat16 g_W2H[256 * 256], g_W2L[256 * 256];

/* ------------------------------------------------------------------ */
/* JAX threefry2x32 noise (partitionable path; verified R4)            */
/* ------------------------------------------------------------------ */
__device__ __forceinline__ uint32_t rotl32(uint32_t x, uint32_t r) {
    return (x << r) | (x >> (32u - r));
}

__device__ __forceinline__ float jax_noise(int s, int r, int d)
{
    uint32_t idx = (uint32_t)((s * NV + r) * 3 + d);
    uint32_t x0 = 0u, x1 = idx;
    const uint32_t K0 = 0u, K1 = 1u, K2 = 0x1BD11BDBu;
    x0 += K0; x1 += K1;
#define QR(rv) { x0 += x1; x1 = rotl32(x1, rv); x1 ^= x0; }
    QR(13) QR(15) QR(26) QR(6)
    x0 += K1; x1 += K2 + 1u;
    QR(17) QR(29) QR(16) QR(24)
    x0 += K2; x1 += K0 + 2u;
    QR(13) QR(15) QR(26) QR(6)
    x0 += K0; x1 += K1 + 3u;
    QR(17) QR(29) QR(16) QR(24)
    x0 += K1; x1 += K2 + 4u;
    QR(13) QR(15) QR(26) QR(6)
    x0 += K2; x1 += K0 + 5u;
#undef QR
    uint32_t bits = x0 ^ x1;
    float f = __uint_as_float((bits >> 9) | 0x3f800000u) - 1.0f;
    const float lo = -0.99999994f;
    float u = fmaxf(lo, f * 2.0f + lo);
    return (1.41421354f * erfinvf(u)) * 5e-4f;
}

/* ------------------------------------------------------------------ */
/* helpers                                                             */
/* ------------------------------------------------------------------ */
__device__ __forceinline__ uint32_t smem_u32(const void* p) {
    uint32_t a;
    asm("{ .reg .u64 t; cvta.to.shared.u64 t, %1; cvt.u32.u64 %0, t; }"
        : "=r"(a) : "l"(p));
    return a;
}

__device__ __forceinline__ void ldsm4(uint32_t* d, uint32_t addr) {
    asm volatile("ldmatrix.sync.aligned.m8n8.x4.shared.b16 {%0,%1,%2,%3}, [%4];"
                 : "=r"(d[0]), "=r"(d[1]), "=r"(d[2]), "=r"(d[3]) : "r"(addr));
}

__device__ __forceinline__ void mma_bf16(float* c, const uint32_t* a, const uint32_t* b) {
    asm volatile("mma.sync.aligned.m16n8k16.row.col.f32.bf16.bf16.f32 "
                 "{%0,%1,%2,%3}, {%4,%5,%6,%7}, {%8,%9}, {%0,%1,%2,%3};"
                 : "+f"(c[0]), "+f"(c[1]), "+f"(c[2]), "+f"(c[3])
                 : "r"(a[0]), "r"(a[1]), "r"(a[2]), "r"(a[3]),
                   "r"(b[0]), "r"(b[1]));
}

#define CP16(dst, src) \
    asm volatile("cp.async.cg.shared.global [%0], [%1], 16;" \
                 :: "r"(dst), "l"(src) : "memory")
#define CP_COMMIT() asm volatile("cp.async.commit_group;" ::: "memory")
#define CP_WAIT(n)  asm volatile("cp.async.wait_group %0;" :: "n"(n) : "memory")

__device__ __forceinline__ void split1(float x, __nv_bfloat16& h, __nv_bfloat16& l) {
    h = __float2bfloat16(x);
    l = __float2bfloat16(x - __bfloat162float(h));
}

/* ------------------------------------------------------------------ */
/* GEMM via mma.sync bf16-split, cp.async double-buffered.             */
/* C[M,Nout] = (Ah+Al)[M,256] @ (Bh+Bl)[Nout,256]^T  (3-product)       */
/* grid (Nout/128, M/128), 256 thr, 8 warps 4m x 2n, warp tile 32x64.  */
/* epi: 0 none | 1 +bias | 2 +bias+leaky (store Cf and/or Ch/Cl)       */
/*      3 +bias+leaky then W3 partial reduction (no C store)           */
/* ------------------------------------------------------------------ */
#define STR   40                              /* smem row stride (bf16) */
#define ARRB  (128 * STR * 2)                 /* bytes per tile: 10240  */
#define STAGEB (4 * ARRB)                     /* bytes per stage: 40960 */
#define GEMM_SMEM (2 * STAGEB)                /* 81920                  */

__global__ void __launch_bounds__(256, 2)
gemm_mma(const __nv_bfloat16* __restrict__ Ah, const __nv_bfloat16* __restrict__ Al,
         const __nv_bfloat16* __restrict__ Bh, const __nv_bfloat16* __restrict__ Bl,
         float* __restrict__ Cf,
         __nv_bfloat16* __restrict__ Ch, __nv_bfloat16* __restrict__ Cl,
         int Nout, const float* __restrict__ bias, int epi,
         const float* __restrict__ W3g, float* __restrict__ part)
{
    extern __shared__ __align__(16) char sm[];
    __shared__ float sW3[768];
    __shared__ float outacc[128][2][3];
    const uint32_t sb = smem_u32(sm);

    const int tid  = threadIdx.x;
    const int lane = tid & 31, w = tid >> 5;
    const int wm = w >> 1, wn = w & 1;
    const int m0 = blockIdx.y * 128, n0 = blockIdx.x * 128;

    if (epi == 3)
        for (int i = tid; i < 768; i += 256) sW3[i] = W3g[i];

    float acc[2][8][4];
#pragma unroll
    for (int i = 0; i < 2; i++)
#pragma unroll
        for (int j = 0; j < 8; j++)
#pragma unroll
            for (int q = 0; q < 4; q++) acc[i][j][q] = 0.f;

    const int lrow = tid >> 1;
    const int lcol = (tid & 1) * 16;
    const size_t aoff = (size_t)(m0 + lrow) * 256 + lcol;
    const size_t boff = (size_t)(n0 + lrow) * 256 + lcol;
    const __nv_bfloat16* src[4] = { Ah + aoff, Al + aoff, Bh + boff, Bl + boff };
    const uint32_t dbase = sb + (uint32_t)(lrow * STR + lcol) * 2u;

    auto load_stage = [&](int kc, int st) {
#pragma unroll
        for (int a = 0; a < 4; a++) {
            const __nv_bfloat16* s = src[a] + kc * 32;
            uint32_t d = dbase + st * STAGEB + a * ARRB;
            CP16(d,      s);
            CP16(d + 16, s + 8);
        }
        CP_COMMIT();
    };

    load_stage(0, 0);

    for (int kc = 0; kc < 8; kc++) {
        if (kc < 7) load_stage(kc + 1, (kc + 1) & 1);
        if (kc < 7) { CP_WAIT(1); } else { CP_WAIT(0); }
        __syncthreads();

        const uint32_t sbase = sb + (kc & 1) * STAGEB;
#pragma unroll
        for (int ks = 0; ks < 2; ks++) {
            uint32_t ah[2][4], alr[2][4];
#pragma unroll
            for (int mt = 0; mt < 2; mt++) {
                uint32_t r = (uint32_t)(wm * 32 + mt * 16 + (lane & 15));
                uint32_t c = (uint32_t)(ks * 16 + (lane >> 4) * 8);
                uint32_t off = sbase + (r * STR + c) * 2;
                ldsm4(ah[mt],  off);
                ldsm4(alr[mt], off + ARRB);
            }
#pragma unroll
            for (int pp = 0; pp < 2; pp++) {
                uint32_t bh[2][4], bl[2][4];
#pragma unroll
                for (int pi = 0; pi < 2; pi++) {
                    const int p = pp * 2 + pi;
                    uint32_t g = lane >> 3, rr = lane & 7;
                    uint32_t r = (uint32_t)(wn * 64 + p * 16 + ((g & 2) ? 8 : 0) + rr);
                    uint32_t c = (uint32_t)(ks * 16 + ((g & 1) ? 8 : 0));
                    uint32_t off = sbase + 2 * ARRB + (r * STR + c) * 2;
                    ldsm4(bh[pi], off);
                    ldsm4(bl[pi], off + ARRB);
                }
#pragma unroll
                for (int pi = 0; pi < 2; pi++)
#pragma unroll
                    for (int mt = 0; mt < 2; mt++)
#pragma unroll
                        for (int q = 0; q < 2; q++)
                            mma_bf16(acc[mt][(pp * 2 + pi) * 2 + q],
                                     ah[mt], &bh[pi][q * 2]);
#pragma unroll
                for (int pi = 0; pi < 2; pi++)
#pragma unroll
                    for (int mt = 0; mt < 2; mt++)
#pragma unroll
                        for (int q = 0; q < 2; q++)
                            mma_bf16(acc[mt][(pp * 2 + pi) * 2 + q],
                                     ah[mt], &bl[pi][q * 2]);
#pragma unroll
                for (int pi = 0; pi < 2; pi++)
#pragma unroll
                    for (int mt = 0; mt < 2; mt++)
#pragma unroll
                        for (int q = 0; q < 2; q++)
                            mma_bf16(acc[mt][(pp * 2 + pi) * 2 + q],
                                     alr[mt], &bh[pi][q * 2]);
            }
        }
        __syncthreads();
    }

    if (epi == 3) {
        /* bias + leaky + W3 partial reduction; D2 never materialized */
        float prt[2][2][3];
#pragma unroll
        for (int mt = 0; mt < 2; mt++)
#pragma unroll
            for (int h = 0; h < 2; h++)
#pragma unroll
                for (int d = 0; d < 3; d++) prt[mt][h][d] = 0.f;

#pragma unroll
        for (int nt = 0; nt < 8; nt++) {
            const int cg = n0 + wn * 64 + nt * 8 + (lane & 3) * 2;
            const float bb0 = bias[cg], bb1 = bias[cg + 1];
#pragma unroll
            for (int mt = 0; mt < 2; mt++)
#pragma unroll
                for (int h = 0; h < 2; h++) {
                    float v0 = acc[mt][nt][h * 2 + 0] + bb0;
                    float v1 = acc[mt][nt][h * 2 + 1] + bb1;
                    v0 = v0 > 0.f ? v0 : 0.1f * v0;
                    v1 = v1 > 0.f ? v1 : 0.1f * v1;
#pragma unroll
                    for (int d = 0; d < 3; d++)
                        prt[mt][h][d] += v0 * sW3[d * 256 + cg]
                                       + v1 * sW3[d * 256 + cg + 1];
                }
        }
#pragma unroll
        for (int mt = 0; mt < 2; mt++)
#pragma unroll
            for (int h = 0; h < 2; h++)
#pragma unroll
                for (int d = 0; d < 3; d++) {
                    float v = prt[mt][h][d];
                    v += __shfl_xor_sync(0xffffffffu, v, 1);
                    v += __shfl_xor_sync(0xffffffffu, v, 2);
                    if ((lane & 3) == 0)
                        outacc[wm * 32 + mt * 16 + h * 8 + (lane >> 2)][wn][d] = v;
                }
        __syncthreads();
        if (tid < 128) {
            float* dst = part + (size_t)blockIdx.x * NV * 3 + (size_t)(m0 + tid) * 3;
#pragma unroll
            for (int d = 0; d < 3; d++)
                dst[d] = outacc[tid][0][d] + outacc[tid][1][d];
        }
        return;
    }

    /* epilogue: stores */
#pragma unroll
    for (int mt = 0; mt < 2; mt++) {
        const int r0 = m0 + wm * 32 + mt * 16 + (lane >> 2);
#pragma unroll
        for (int nt = 0; nt < 8; nt++) {
            const int c0 = n0 + wn * 64 + nt * 8 + (lane & 3) * 2;
            float b0 = 0.f, b1 = 0.f;
            if (bias) { b0 = bias[c0]; b1 = bias[c0 + 1]; }
#pragma unroll
            for (int h = 0; h < 2; h++) {
                const int r = r0 + h * 8;
                float v0 = acc[mt][nt][h * 2 + 0] + b0;
                float v1 = acc[mt][nt][h * 2 + 1] + b1;
                if (epi == 2) {
                    v0 = v0 > 0.f ? v0 : 0.1f * v0;
                    v1 = v1 > 0.f ? v1 : 0.1f * v1;
                }
                const size_t o = (size_t)r * Nout + c0;
                if (Cf) *(float2*)(Cf + o) = make_float2(v0, v1);
                if (Ch) {
                    __nv_bfloat16 h0, l0, h1, l1;
                    split1(v0, h0, l0);
                    split1(v1, h1, l1);
                    *(uint32_t*)(Ch + o) =
                        ((uint32_t)__bfloat16_as_ushort(h1) << 16) | __bfloat16_as_ushort(h0);
                    *(uint32_t*)(Cl + o) =
                        ((uint32_t)__bfloat16_as_ushort(l1) << 16) | __bfloat16_as_ushort(l0);
                }
            }
        }
    }
}

/* ------------------------------------------------------------------ */
/* Graph mix: M[(n,w),c] = sum_{k,v} Y[(n,v),k*256+c] * Aadj[k,v,w]    */
/* ------------------------------------------------------------------ */
__global__ void __launch_bounds__(256)
graphmix_kernel(const float* __restrict__ Y,
                __nv_bfloat16* __restrict__ Mh, __nv_bfloat16* __restrict__ Ml)
{
    __shared__ __align__(16) float sA[K_N * V_N * 28];
    const int n = blockIdx.x;
    const int tid = threadIdx.x;
    for (int i = tid; i < K_N * V_N * 28; i += 256) sA[i] = g_Aadj[i];
    __syncthreads();

    const float* Yn = Y + (size_t)n * V_N * 768;
    const int c = tid;
    float acc[28];
#pragma unroll
    for (int w = 0; w < 28; w++) acc[w] = 0.f;

#pragma unroll
    for (int k = 0; k < K_N; k++) {
#pragma unroll
        for (int v = 0; v < V_N; v++) {
            float yv = Yn[v * 768 + k * 256 + c];
            const float4* arow = (const float4*)&sA[(k * V_N + v) * 28];
#pragma unroll
            for (int q = 0; q < 7; q++) {
                float4 a4 = arow[q];
                acc[q * 4 + 0] += yv * a4.x;
                acc[q * 4 + 1] += yv * a4.y;
                acc[q * 4 + 2] += yv * a4.z;
                acc[q * 4 + 3] += yv * a4.w;
            }
        }
    }
    for (int w = 0; w < V_N; w++) {
        __nv_bfloat16 h, l;
        split1(acc[w], h, l);
        const size_t o = ((size_t)n * V_N + w) * 256 + c;
        Mh[o] = h;
        Ml[o] = l;
    }
}

/* ------------------------------------------------------------------ */
/* GRU elementwise (thin: one block per row — proven fastest in R8)    */
/* ------------------------------------------------------------------ */
__global__ void __launch_bounds__(256)
gru_kernel(const float* __restrict__ H, const float* __restrict__ G,
           const float* __restrict__ P1, const float* __restrict__ P2,
           const float* __restrict__ P3,
           const float* __restrict__ Wir, const float* __restrict__ bir,
           const float* __restrict__ Wii, const float* __restrict__ bii,
           const float* __restrict__ Win, const float* __restrict__ bin,
           float* __restrict__ Hnew,
           __nv_bfloat16* __restrict__ Hh, __nv_bfloat16* __restrict__ Hl,
           int s)
{
    const int r = blockIdx.x;
    const int c = threadIdx.x;
    __shared__ float sx[9];
    if (c < 3) {
        float h1 = P1[r * 3 + c], h2 = P2[r * 3 + c], h3 = P3[r * 3 + c];
        float nz = jax_noise(s, r, c);
        float insv = h2 - h3;
        sx[c]     = h1 + nz;
        sx[3 + c] = insv;
        sx[6 + c] = (h1 - h2) - insv;
    }
    __syncthreads();

    float xr = bir[c], xi = bii[c], xn = bin[c];
#pragma unroll
    for (int d = 0; d < 9; d++) {
        float xv = sx[d];
        xr += xv * Wir[c * 9 + d];
        xi += xv * Wii[c * 9 + d];
        xn += xv * Win[c * 9 + d];
    }
    size_t g = (size_t)r * 768;
    float gr = G[g + c], gi = G[g + 256 + c], gh = G[g + 512 + c];
    float rg = 1.f / (1.f + expf(-(xr + gr)));
    float zg = 1.f / (1.f + expf(-(xi + gi)));
    float nn = tanhf(xn + rg * gh);
    float hp = H[(size_t)r * 256 + c];
    float hv = (1.f - zg) * nn + zg * hp;
    const size_t o = (size_t)r * 256 + c;
    Hnew[o] = hv;
    __nv_bfloat16 hh, hl;
    split1(hv, hh, hl);
    Hh[o] = hh;
    Hl[o] = hl;
}

/* ------------------------------------------------------------------ */
/* Combine W3 partials: pred = P1 + noise + (part0 + part1 + b3)       */
/* ------------------------------------------------------------------ */
__global__ void __launch_bounds__(256)
out_combine(const float* __restrict__ part,
            const float* __restrict__ b3, const float* __restrict__ P1,
            float* __restrict__ Pnew, float* __restrict__ out, int s)
{
    const int r = blockIdx.x * 256 + threadIdx.x;
#pragma unroll
    for (int d = 0; d < 3; d++) {
        float res = part[(size_t)r * 3 + d]
                  + part[(size_t)NV * 3 + (size_t)r * 3 + d] + b3[d];
        float p = (P1[r * 3 + d] + jax_noise(s, r, d)) + res;
        Pnew[r * 3 + d] = p;
        out[((size_t)r * TS + s) * 3 + d] = p;
    }
}

/* ------------------------------------------------------------------ */
/* Prep kernels                                                        */
/* ------------------------------------------------------------------ */
__global__ void prep_aadj(const float* __restrict__ A,
                          const float* __restrict__ em,
                          const float* __restrict__ ea)
{
    int i = blockIdx.x * 256 + threadIdx.x;
    if (i >= K_N * V_N * 28) return;
    int w = i % 28, kv = i / 28;
    g_Aadj[i] = (w < V_N) ? (A[kv * V_N + w] * em[kv * V_N + w] + ea[kv * V_N + w])
                          : 0.f;
}

__global__ void split_weights(const float* __restrict__ conv_w,
                              const float* __restrict__ Whr,
                              const float* __restrict__ Whi,
                              const float* __restrict__ Whh,
                              const float* __restrict__ W1,
                              const float* __restrict__ W2)
{
    int i = blockIdx.x * 256 + threadIdx.x;  /* 524288 total */
    const float* src;
    __nv_bfloat16 *dh, *dl;
    int off;
    if (i < 196608)       { src = conv_w; dh = g_cwH; dl = g_cwL; off = i; }
    else if (i < 262144)  { src = Whr; dh = g_WhH; dl = g_WhL; off = i - 196608; }
    else if (i < 327680)  { src = Whi; dh = g_WhH + 65536; dl = g_WhL + 65536; off = i - 262144; }
    else if (i < 393216)  { src = Whh; dh = g_WhH + 131072; dl = g_WhL + 131072; off = i - 327680; }
    else if (i < 458752)  { src = W1; dh = g_W1H; dl = g_W1L; off = i - 393216; }
    else                  { src = W2; dh = g_W2H; dl = g_W2L; off = i - 458752; }
    __nv_bfloat16 h, l;
    split1(src[off], h, l);
    dh[off] = h;
    dl[off] = l;
}

/* hidden [N,C,V] -> H [(n,v),c] fp32 + split, one block per n */
__global__ void __launch_bounds__(256)
transpose_h(const float* __restrict__ hid, float* __restrict__ H,
            __nv_bfloat16* __restrict__ Hh, __nv_bfloat16* __restrict__ Hl)
{
    __shared__ float sm[C_N * V_N];
    const int n = blockIdx.x;
    const float* src = hid + (size_t)n * C_N * V_N;
    for (int i = threadIdx.x; i < C_N * V_N; i += 256) sm[i] = src[i];
    __syncthreads();
    const size_t base = (size_t)n * V_N * C_N;
    for (int i = threadIdx.x; i < C_N * V_N; i += 256) {
        int v = i >> 8, c = i & 255;
        float x = sm[c * V_N + v];
        H[base + i] = x;
        __nv_bfloat16 hh, ll;
        split1(x, hh, ll);
        Hh[base + i] = hh;
        Hl[base + i] = ll;
    }
}

/* ------------------------------------------------------------------ */
/* Host driver                                                         */
/* ------------------------------------------------------------------ */
extern "C" void kernel_launch(void* const* d_in, const int* in_sizes, int n_in,
                              void* d_out, int out_size)
{
    const float* in0    = (const float*)d_in[0];
    const float* in1    = (const float*)d_in[1];
    const float* in2    = (const float*)d_in[2];
    const float* hidden = (const float*)d_in[3];
    const float* A      = (const float*)d_in[4];
    const float* emul   = (const float*)d_in[5];
    const float* eadd   = (const float*)d_in[6];
    const float* conv_w = (const float*)d_in[7];
    const float* conv_b = (const float*)d_in[8];
    const float* Wir    = (const float*)d_in[9];
    const float* bir    = (const float*)d_in[10];
    const float* Wii    = (const float*)d_in[11];
    const float* bii    = (const float*)d_in[12];
    const float* Win    = (const float*)d_in[13];
    const float* b_in   = (const float*)d_in[14];
    const float* Whr    = (const float*)d_in[15];
    const float* Whi    = (const float*)d_in[16];
    const float* Whh    = (const float*)d_in[17];
    const float* W1     = (const float*)d_in[18];
    const float* b1     = (const float*)d_in[19];
    const float* W2     = (const float*)d_in[20];
    const float* b2     = (const float*)d_in[21];
    const float* W3     = (const float*)d_in[22];
    const float* b3     = (const float*)d_in[23];
    float* out = (float*)d_out;

    float *pHA, *pHB, *pY, *pG, *pPbase, *pPart;
    cudaGetSymbolAddress((void**)&pHA, g_HA);
    cudaGetSymbolAddress((void**)&pHB, g_HB);
    cudaGetSymbolAddress((void**)&pY,  g_Y);
    cudaGetSymbolAddress((void**)&pG,  g_G);
    cudaGetSymbolAddress((void**)&pPbase, g_P);
    cudaGetSymbolAddress((void**)&pPart,  g_part);

    __nv_bfloat16 *pHAh, *pHAl, *pHBh, *pHBl, *pMh, *pMl, *pD1h, *pD1l;
    __nv_bfloat16 *pcwH, *pcwL, *pWhH, *pWhL, *pW1H, *pW1L, *pW2H, *pW2L;
    cudaGetSymbolAddress((void**)&pHAh, g_HAh);
    cudaGetSymbolAddress((void**)&pHAl, g_HAl);
    cudaGetSymbolAddress((void**)&pHBh, g_HBh);
    cudaGetSymbolAddress((void**)&pHBl, g_HBl);
    cudaGetSymbolAddress((void**)&pMh,  g_Mh);
    cudaGetSymbolAddress((void**)&pMl,  g_Ml);
    cudaGetSymbolAddress((void**)&pD1h, g_D1h);
    cudaGetSymbolAddress((void**)&pD1l, g_D1l);
    cudaGetSymbolAddress((void**)&pcwH, g_cwH);
    cudaGetSymbolAddress((void**)&pcwL, g_cwL);
    cudaGetSymbolAddress((void**)&pWhH, g_WhH);
    cudaGetSymbolAddress((void**)&pWhL, g_WhL);
    cudaGetSymbolAddress((void**)&pW1H, g_W1H);
    cudaGetSymbolAddress((void**)&pW1L, g_W1L);
    cudaGetSymbolAddress((void**)&pW2H, g_W2H);
    cudaGetSymbolAddress((void**)&pW2L, g_W2L);

    float* Pbuf[4];
    for (int i = 0; i < 4; i++) Pbuf[i] = pPbase + (size_t)i * NV * 3;

    cudaFuncSetAttribute(gemm_mma,
                         cudaFuncAttributeMaxDynamicSharedMemorySize, GEMM_SMEM);

    /* per-launch prep */
    prep_aadj<<<(K_N * V_N * 28 + 255) / 256, 256>>>(A, emul, eadd);
    transpose_h<<<N_BATCH, 256>>>(hidden, pHA, pHAh, pHAl);
    split_weights<<<524288 / 256, 256>>>(conv_w, Whr, Whi, Whh, W1, W2);
    cudaMemcpyAsync(Pbuf[0], in0, (size_t)NV * 3 * sizeof(float),
                    cudaMemcpyDeviceToDevice, 0);
    cudaMemcpyAsync(Pbuf[1], in1, (size_t)NV * 3 * sizeof(float),
                    cudaMemcpyDeviceToDevice, 0);
    cudaMemcpyAsync(Pbuf[2], in2, (size_t)NV * 3 * sizeof(float),
                    cudaMemcpyDeviceToDevice, 0);

    const dim3 grid768(6, NV / 128);
    const dim3 grid256(2, NV / 128);

    for (int s = 0; s < TS; s++) {
        float* Hcur  = (s & 1) ? pHB : pHA;
        float* Hnext = (s & 1) ? pHA : pHB;
        const __nv_bfloat16* Hch = (s & 1) ? pHBh : pHAh;
        const __nv_bfloat16* Hcl = (s & 1) ? pHBl : pHAl;
        __nv_bfloat16* Hnh = (s & 1) ? pHAh : pHBh;
        __nv_bfloat16* Hnl = (s & 1) ? pHAl : pHBl;

        const __nv_bfloat16 *GAh = Hch, *GAl = Hcl;
        if (s < 10) {
            gemm_mma<<<grid768, 256, GEMM_SMEM>>>(Hch, Hcl, pcwH, pcwL,
                                                  pY, nullptr, nullptr,
                                                  768, conv_b, 1, nullptr, nullptr);
            graphmix_kernel<<<N_BATCH, 256>>>(pY, pMh, pMl);
            GAh = pMh;
            GAl = pMl;
        }

        gemm_mma<<<grid768, 256, GEMM_SMEM>>>(GAh, GAl, pWhH, pWhL,
                                              pG, nullptr, nullptr,
                                              768, nullptr, 0, nullptr, nullptr);

        int m4 = s & 3;
        int i1   = (4 - m4) & 3;
        int i2   = (5 - m4) & 3;
        int i3   = (6 - m4) & 3;
        int inew = (7 - m4) & 3;

        gru_kernel<<<NV, 256>>>(Hcur, pG, Pbuf[i1], Pbuf[i2], Pbuf[i3],
                                Wir, bir, Wii, bii, Win, b_in,
                                Hnext, Hnh, Hnl, s);

        gemm_mma<<<grid256, 256, GEMM_SMEM>>>(Hnh, Hnl, pW1H, pW1L,
                                              nullptr, pD1h, pD1l,
                                              256, b1, 2, nullptr, nullptr);
        /* W2 GEMM with fused W3 projection: emits 3 partials/row */
        gemm_mma<<<grid256, 256, GEMM_SMEM>>>(pD1h, pD1l, pW2H, pW2L,
                                              nullptr, nullptr, nullptr,
                                              256, b2, 3, W3, pPart);

        out_combine<<<NV / 256, 256>>>(pPart, b3, Pbuf[i1], Pbuf[inew], out, s);
    }
}

// round 14
// speedup vs baseline: 1.0009x; 1.0007x over previous
#include <cuda_runtime.h>
#include <cuda_bf16.h>
#include <math.h>
#include <stdint.h>

#define N_BATCH 4096
#define V_N     26
#define C_N     256
#define K_N     3
#define NV      (N_BATCH * V_N)            /* 106496 */
#define TS      25

/* ------------------------------------------------------------------ */
/* Device scratch (no cudaMalloc allowed)                              */
/* ------------------------------------------------------------------ */
__device__ float g_HA[(size_t)NV * C_N];        /* hidden fp32 ping    */
__device__ float g_HB[(size_t)NV * C_N];        /* hidden fp32 pong    */
__device__ float g_Y [(size_t)NV * 3 * C_N];    /* conv out fp32       */
__device__ float g_G [(size_t)NV * 3 * C_N];    /* gate pre-act fp32   */
__device__ float g_P [4][(size_t)NV * 3];       /* pred history ring   */
__device__ float g_part[2][(size_t)NV * 3];     /* W3 partials         */
__device__ __align__(16) float g_Aadj[K_N * V_N * 28];

/* bf16 hi/lo split activation buffers */
__device__ __nv_bfloat16 g_HAh[(size_t)NV * C_N], g_HAl[(size_t)NV * C_N];
__device__ __nv_bfloat16 g_HBh[(size_t)NV * C_N], g_HBl[(size_t)NV * C_N];
__device__ __nv_bfloat16 g_Mh [(size_t)NV * C_N], g_Ml [(size_t)NV * C_N];
__device__ __nv_bfloat16 g_D1h[(size_t)NV * C_N], g_D1l[(size_t)NV * C_N];

/* bf16 hi/lo split weights */
__device__ __nv_bfloat16 g_cwH[768 * 256], g_cwL[768 * 256];
__device__ __nv_bfloat16 g_WhH[768 * 256], g_WhL[768 * 256];
__device__ __nv_bfloat16 g_W1H[256 * 256], g_W1L[256 * 256];
__device__ __nv_bfloat16 g_W2H[256 * 256], g_W2L[256 * 256];

/* ------------------------------------------------------------------ */
/* JAX threefry2x32 noise (partitionable path; verified R4)            */
/* ------------------------------------------------------------------ */
__device__ __forceinline__ uint32_t rotl32(uint32_t x, uint32_t r) {
    return (x << r) | (x >> (32u - r));
}

__device__ __forceinline__ float jax_noise(int s, int r, int d)
{
    uint32_t idx = (uint32_t)((s * NV + r) * 3 + d);
    uint32_t x0 = 0u, x1 = idx;
    const uint32_t K0 = 0u, K1 = 1u, K2 = 0x1BD11BDBu;
    x0 += K0; x1 += K1;
#define QR(rv) { x0 += x1; x1 = rotl32(x1, rv); x1 ^= x0; }
    QR(13) QR(15) QR(26) QR(6)
    x0 += K1; x1 += K2 + 1u;
    QR(17) QR(29) QR(16) QR(24)
    x0 += K2; x1 += K0 + 2u;
    QR(13) QR(15) QR(26) QR(6)
    x0 += K0; x1 += K1 + 3u;
    QR(17) QR(29) QR(16) QR(24)
    x0 += K1; x1 += K2 + 4u;
    QR(13) QR(15) QR(26) QR(6)
    x0 += K2; x1 += K0 + 5u;
#undef QR
    uint32_t bits = x0 ^ x1;
    float f = __uint_as_float((bits >> 9) | 0x3f800000u) - 1.0f;
    const float lo = -0.99999994f;
    float u = fmaxf(lo, f * 2.0f + lo);
    return (1.41421354f * erfinvf(u)) * 5e-4f;
}

/* ------------------------------------------------------------------ */
/* helpers                                                             */
/* ------------------------------------------------------------------ */
__device__ __forceinline__ uint32_t smem_u32(const void* p) {
    uint32_t a;
    asm("{ .reg .u64 t; cvta.to.shared.u64 t, %1; cvt.u32.u64 %0, t; }"
        : "=r"(a) : "l"(p));
    return a;
}

__device__ __forceinline__ void ldsm4(uint32_t* d, uint32_t addr) {
    asm volatile("ldmatrix.sync.aligned.m8n8.x4.shared.b16 {%0,%1,%2,%3}, [%4];"
                 : "=r"(d[0]), "=r"(d[1]), "=r"(d[2]), "=r"(d[3]) : "r"(addr));
}

__device__ __forceinline__ void mma_bf16(float* c, const uint32_t* a, const uint32_t* b) {
    asm volatile("mma.sync.aligned.m16n8k16.row.col.f32.bf16.bf16.f32 "
                 "{%0,%1,%2,%3}, {%4,%5,%6,%7}, {%8,%9}, {%0,%1,%2,%3};"
                 : "+f"(c[0]), "+f"(c[1]), "+f"(c[2]), "+f"(c[3])
                 : "r"(a[0]), "r"(a[1]), "r"(a[2]), "r"(a[3]),
                   "r"(b[0]), "r"(b[1]));
}

#define CP16(dst, src) \
    asm volatile("cp.async.cg.shared.global [%0], [%1], 16;" \
                 :: "r"(dst), "l"(src) : "memory")
#define CP_COMMIT() asm volatile("cp.async.commit_group;" ::: "memory")
#define CP_WAIT(n)  asm volatile("cp.async.wait_group %0;" :: "n"(n) : "memory")

__device__ __forceinline__ void split1(float x, __nv_bfloat16& h, __nv_bfloat16& l) {
    h = __float2bfloat16(x);
    l = __float2bfloat16(x - __bfloat162float(h));
}

/* ------------------------------------------------------------------ */
/* GEMM via mma.sync bf16-split, cp.async double-buffered.             */
/* C[M,Nout] = (Ah+Al)[M,256] @ (Bh+Bl)[Nout,256]^T  (3-product)       */
/* grid (Nout/128, M/128), 256 thr, 8 warps 4m x 2n, warp tile 32x64.  */
/* epi: 0 none | 1 +bias | 2 +bias+leaky (store Cf and/or Ch/Cl)       */
/*      3 +bias+leaky then W3 partial reduction (no C store)           */
/* ------------------------------------------------------------------ */
#define STR   40                              /* smem row stride (bf16) */
#define ARRB  (128 * STR * 2)                 /* bytes per tile: 10240  */
#define STAGEB (4 * ARRB)                     /* bytes per stage: 40960 */
#define GEMM_SMEM (2 * STAGEB)                /* 81920                  */

__global__ void __launch_bounds__(256, 2)
gemm_mma(const __nv_bfloat16* __restrict__ Ah, const __nv_bfloat16* __restrict__ Al,
         const __nv_bfloat16* __restrict__ Bh, const __nv_bfloat16* __restrict__ Bl,
         float* __restrict__ Cf,
         __nv_bfloat16* __restrict__ Ch, __nv_bfloat16* __restrict__ Cl,
         int Nout, const float* __restrict__ bias, int epi,
         const float* __restrict__ W3g, float* __restrict__ part)
{
    extern __shared__ __align__(16) char sm[];
    __shared__ float sW3[768];
    __shared__ float outacc[128][2][3];
    const uint32_t sb = smem_u32(sm);

    const int tid  = threadIdx.x;
    const int lane = tid & 31, w = tid >> 5;
    const int wm = w >> 1, wn = w & 1;
    const int m0 = blockIdx.y * 128, n0 = blockIdx.x * 128;

    if (epi == 3)
        for (int i = tid; i < 768; i += 256) sW3[i] = W3g[i];

    float acc[2][8][4];
#pragma unroll
    for (int i = 0; i < 2; i++)
#pragma unroll
        for (int j = 0; j < 8; j++)
#pragma unroll
            for (int q = 0; q < 4; q++) acc[i][j][q] = 0.f;

    const int lrow = tid >> 1;
    const int lcol = (tid & 1) * 16;
    const size_t aoff = (size_t)(m0 + lrow) * 256 + lcol;
    const size_t boff = (size_t)(n0 + lrow) * 256 + lcol;
    const __nv_bfloat16* src[4] = { Ah + aoff, Al + aoff, Bh + boff, Bl + boff };
    const uint32_t dbase = sb + (uint32_t)(lrow * STR + lcol) * 2u;

    auto load_stage = [&](int kc, int st) {
#pragma unroll
        for (int a = 0; a < 4; a++) {
            const __nv_bfloat16* s = src[a] + kc * 32;
            uint32_t d = dbase + st * STAGEB + a * ARRB;
            CP16(d,      s);
            CP16(d + 16, s + 8);
        }
        CP_COMMIT();
    };

    load_stage(0, 0);

    for (int kc = 0; kc < 8; kc++) {
        if (kc < 7) load_stage(kc + 1, (kc + 1) & 1);
        if (kc < 7) { CP_WAIT(1); } else { CP_WAIT(0); }
        __syncthreads();

        const uint32_t sbase = sb + (kc & 1) * STAGEB;
#pragma unroll
        for (int ks = 0; ks < 2; ks++) {
            uint32_t ah[2][4], alr[2][4];
#pragma unroll
            for (int mt = 0; mt < 2; mt++) {
                uint32_t r = (uint32_t)(wm * 32 + mt * 16 + (lane & 15));
                uint32_t c = (uint32_t)(ks * 16 + (lane >> 4) * 8);
                uint32_t off = sbase + (r * STR + c) * 2;
                ldsm4(ah[mt],  off);
                ldsm4(alr[mt], off + ARRB);
            }
#pragma unroll
            for (int pp = 0; pp < 2; pp++) {
                uint32_t bh[2][4], bl[2][4];
#pragma unroll
                for (int pi = 0; pi < 2; pi++) {
                    const int p = pp * 2 + pi;
                    uint32_t g = lane >> 3, rr = lane & 7;
                    uint32_t r = (uint32_t)(wn * 64 + p * 16 + ((g & 2) ? 8 : 0) + rr);
                    uint32_t c = (uint32_t)(ks * 16 + ((g & 1) ? 8 : 0));
                    uint32_t off = sbase + 2 * ARRB + (r * STR + c) * 2;
                    ldsm4(bh[pi], off);
                    ldsm4(bl[pi], off + ARRB);
                }
#pragma unroll
                for (int pi = 0; pi < 2; pi++)
#pragma unroll
                    for (int mt = 0; mt < 2; mt++)
#pragma unroll
                        for (int q = 0; q < 2; q++)
                            mma_bf16(acc[mt][(pp * 2 + pi) * 2 + q],
                                     ah[mt], &bh[pi][q * 2]);
#pragma unroll
                for (int pi = 0; pi < 2; pi++)
#pragma unroll
                    for (int mt = 0; mt < 2; mt++)
#pragma unroll
                        for (int q = 0; q < 2; q++)
                            mma_bf16(acc[mt][(pp * 2 + pi) * 2 + q],
                                     ah[mt], &bl[pi][q * 2]);
#pragma unroll
                for (int pi = 0; pi < 2; pi++)
#pragma unroll
                    for (int mt = 0; mt < 2; mt++)
#pragma unroll
                        for (int q = 0; q < 2; q++)
                            mma_bf16(acc[mt][(pp * 2 + pi) * 2 + q],
                                     alr[mt], &bh[pi][q * 2]);
            }
        }
        __syncthreads();
    }

    if (epi == 3) {
        /* bias + leaky + W3 partial reduction; D2 never materialized */
        float prt[2][2][3];
#pragma unroll
        for (int mt = 0; mt < 2; mt++)
#pragma unroll
            for (int h = 0; h < 2; h++)
#pragma unroll
                for (int d = 0; d < 3; d++) prt[mt][h][d] = 0.f;

#pragma unroll
        for (int nt = 0; nt < 8; nt++) {
            const int cg = n0 + wn * 64 + nt * 8 + (lane & 3) * 2;
            const float bb0 = bias[cg], bb1 = bias[cg + 1];
#pragma unroll
            for (int mt = 0; mt < 2; mt++)
#pragma unroll
                for (int h = 0; h < 2; h++) {
                    float v0 = acc[mt][nt][h * 2 + 0] + bb0;
                    float v1 = acc[mt][nt][h * 2 + 1] + bb1;
                    v0 = v0 > 0.f ? v0 : 0.1f * v0;
                    v1 = v1 > 0.f ? v1 : 0.1f * v1;
#pragma unroll
                    for (int d = 0; d < 3; d++)
                        prt[mt][h][d] += v0 * sW3[d * 256 + cg]
                                       + v1 * sW3[d * 256 + cg + 1];
                }
        }
#pragma unroll
        for (int mt = 0; mt < 2; mt++)
#pragma unroll
            for (int h = 0; h < 2; h++)
#pragma unroll
                for (int d = 0; d < 3; d++) {
                    float v = prt[mt][h][d];
                    v += __shfl_xor_sync(0xffffffffu, v, 1);
                    v += __shfl_xor_sync(0xffffffffu, v, 2);
                    if ((lane & 3) == 0)
                        outacc[wm * 32 + mt * 16 + h * 8 + (lane >> 2)][wn][d] = v;
                }
        __syncthreads();
        if (tid < 128) {
            float* dst = part + (size_t)blockIdx.x * NV * 3 + (size_t)(m0 + tid) * 3;
#pragma unroll
            for (int d = 0; d < 3; d++)
                dst[d] = outacc[tid][0][d] + outacc[tid][1][d];
        }
        return;
    }

    /* epilogue: stores */
#pragma unroll
    for (int mt = 0; mt < 2; mt++) {
        const int r0 = m0 + wm * 32 + mt * 16 + (lane >> 2);
#pragma unroll
        for (int nt = 0; nt < 8; nt++) {
            const int c0 = n0 + wn * 64 + nt * 8 + (lane & 3) * 2;
            float b0 = 0.f, b1 = 0.f;
            if (bias) { b0 = bias[c0]; b1 = bias[c0 + 1]; }
#pragma unroll
            for (int h = 0; h < 2; h++) {
                const int r = r0 + h * 8;
                float v0 = acc[mt][nt][h * 2 + 0] + b0;
                float v1 = acc[mt][nt][h * 2 + 1] + b1;
                if (epi == 2) {
                    v0 = v0 > 0.f ? v0 : 0.1f * v0;
                    v1 = v1 > 0.f ? v1 : 0.1f * v1;
                }
                const size_t o = (size_t)r * Nout + c0;
                if (Cf) *(float2*)(Cf + o) = make_float2(v0, v1);
                if (Ch) {
                    __nv_bfloat16 h0, l0, h1, l1;
                    split1(v0, h0, l0);
                    split1(v1, h1, l1);
                    *(uint32_t*)(Ch + o) =
                        ((uint32_t)__bfloat16_as_ushort(h1) << 16) | __bfloat16_as_ushort(h0);
                    *(uint32_t*)(Cl + o) =
                        ((uint32_t)__bfloat16_as_ushort(l1) << 16) | __bfloat16_as_ushort(l0);
                }
            }
        }
    }
}

/* ------------------------------------------------------------------ */
/* Graph mix: M[(n,w),c] = sum_{k,v} Y[(n,v),k*256+c] * Aadj[k,v,w]    */
/* ------------------------------------------------------------------ */
__global__ void __launch_bounds__(256)
graphmix_kernel(const float* __restrict__ Y,
                __nv_bfloat16* __restrict__ Mh, __nv_bfloat16* __restrict__ Ml)
{
    __shared__ __align__(16) float sA[K_N * V_N * 28];
    const int n = blockIdx.x;
    const int tid = threadIdx.x;
    for (int i = tid; i < K_N * V_N * 28; i += 256) sA[i] = g_Aadj[i];
    __syncthreads();

    const float* Yn = Y + (size_t)n * V_N * 768;
    const int c = tid;
    float acc[28];
#pragma unroll
    for (int w = 0; w < 28; w++) acc[w] = 0.f;

#pragma unroll
    for (int k = 0; k < K_N; k++) {
#pragma unroll
        for (int v = 0; v < V_N; v++) {
            float yv = Yn[v * 768 + k * 256 + c];
            const float4* arow = (const float4*)&sA[(k * V_N + v) * 28];
#pragma unroll
            for (int q = 0; q < 7; q++) {
                float4 a4 = arow[q];
                acc[q * 4 + 0] += yv * a4.x;
                acc[q * 4 + 1] += yv * a4.y;
                acc[q * 4 + 2] += yv * a4.z;
                acc[q * 4 + 3] += yv * a4.w;
            }
        }
    }
    for (int w = 0; w < V_N; w++) {
        __nv_bfloat16 h, l;
        split1(acc[w], h, l);
        const size_t o = ((size_t)n * V_N + w) * 256 + c;
        Mh[o] = h;
        Ml[o] = l;
    }
}

/* ------------------------------------------------------------------ */
/* GRU elementwise (thin: one block per row — proven fastest in R8)    */
/* ------------------------------------------------------------------ */
__global__ void __launch_bounds__(256)
gru_kernel(const float* __restrict__ H, const float* __restrict__ G,
           const float* __restrict__ P1, const float* __restrict__ P2,
           const float* __restrict__ P3,
           const float* __restrict__ Wir, const float* __restrict__ bir,
           const float* __restrict__ Wii, const float* __restrict__ bii,
           const float* __restrict__ Win, const float* __restrict__ bin,
           float* __restrict__ Hnew,
           __nv_bfloat16* __restrict__ Hh, __nv_bfloat16* __restrict__ Hl,
           int s)
{
    const int r = blockIdx.x;
    const int c = threadIdx.x;
    __shared__ float sx[9];
    if (c < 3) {
        float h1 = P1[r * 3 + c], h2 = P2[r * 3 + c], h3 = P3[r * 3 + c];
        float nz = jax_noise(s, r, c);
        float insv = h2 - h3;
        sx[c]     = h1 + nz;
        sx[3 + c] = insv;
        sx[6 + c] = (h1 - h2) - insv;
    }
    __syncthreads();

    float xr = bir[c], xi = bii[c], xn = bin[c];
#pragma unroll
    for (int d = 0; d < 9; d++) {
        float xv = sx[d];
        xr += xv * Wir[c * 9 + d];
        xi += xv * Wii[c * 9 + d];
        xn += xv * Win[c * 9 + d];
    }
    size_t g = (size_t)r * 768;
    float gr = G[g + c], gi = G[g + 256 + c], gh = G[g + 512 + c];
    float rg = 1.f / (1.f + expf(-(xr + gr)));
    float zg = 1.f / (1.f + expf(-(xi + gi)));
    float nn = tanhf(xn + rg * gh);
    float hp = H[(size_t)r * 256 + c];
    float hv = (1.f - zg) * nn + zg * hp;
    const size_t o = (size_t)r * 256 + c;
    Hnew[o] = hv;
    __nv_bfloat16 hh, hl;
    split1(hv, hh, hl);
    Hh[o] = hh;
    Hl[o] = hl;
}

/* ------------------------------------------------------------------ */
/* Combine W3 partials: pred = P1 + noise + (part0 + part1 + b3)       */
/* ------------------------------------------------------------------ */
__global__ void __launch_bounds__(256)
out_combine(const float* __restrict__ part,
            const float* __restrict__ b3, const float* __restrict__ P1,
            float* __restrict__ Pnew, float* __restrict__ out, int s)
{
    const int r = blockIdx.x * 256 + threadIdx.x;
#pragma unroll
    for (int d = 0; d < 3; d++) {
        float res = part[(size_t)r * 3 + d]
                  + part[(size_t)NV * 3 + (size_t)r * 3 + d] + b3[d];
        float p = (P1[r * 3 + d] + jax_noise(s, r, d)) + res;
        Pnew[r * 3 + d] = p;
        out[((size_t)r * TS + s) * 3 + d] = p;
    }
}

/* ------------------------------------------------------------------ */
/* Prep kernels                                                        */
/* ------------------------------------------------------------------ */
__global__ void prep_aadj(const float* __restrict__ A,
                          const float* __restrict__ em,
                          const float* __restrict__ ea)
{
    int i = blockIdx.x * 256 + threadIdx.x;
    if (i >= K_N * V_N * 28) return;
    int w = i % 28, kv = i / 28;
    g_Aadj[i] = (w < V_N) ? (A[kv * V_N + w] * em[kv * V_N + w] + ea[kv * V_N + w])
                          : 0.f;
}

__global__ void split_weights(const float* __restrict__ conv_w,
                              const float* __restrict__ Whr,
                              const float* __restrict__ Whi,
                              const float* __restrict__ Whh,
                              const float* __restrict__ W1,
                              const float* __restrict__ W2)
{
    int i = blockIdx.x * 256 + threadIdx.x;  /* 524288 total */
    const float* src;
    __nv_bfloat16 *dh, *dl;
    int off;
    if (i < 196608)       { src = conv_w; dh = g_cwH; dl = g_cwL; off = i; }
    else if (i < 262144)  { src = Whr; dh = g_WhH; dl = g_WhL; off = i - 196608; }
    else if (i < 327680)  { src = Whi; dh = g_WhH + 65536; dl = g_WhL + 65536; off = i - 262144; }
    else if (i < 393216)  { src = Whh; dh = g_WhH + 131072; dl = g_WhL + 131072; off = i - 327680; }
    else if (i < 458752)  { src = W1; dh = g_W1H; dl = g_W1L; off = i - 393216; }
    else                  { src = W2; dh = g_W2H; dl = g_W2L; off = i - 458752; }
    __nv_bfloat16 h, l;
    split1(src[off], h, l);
    dh[off] = h;
    dl[off] = l;
}

/* hidden [N,C,V] -> H [(n,v),c] fp32 + split, one block per n */
__global__ void __launch_bounds__(256)
transpose_h(const float* __restrict__ hid, float* __restrict__ H,
            __nv_bfloat16* __restrict__ Hh, __nv_bfloat16* __restrict__ Hl)
{
    __shared__ float sm[C_N * V_N];
    const int n = blockIdx.x;
    const float* src = hid + (size_t)n * C_N * V_N;
    for (int i = threadIdx.x; i < C_N * V_N; i += 256) sm[i] = src[i];
    __syncthreads();
    const size_t base = (size_t)n * V_N * C_N;
    for (int i = threadIdx.x; i < C_N * V_N; i += 256) {
        int v = i >> 8, c = i & 255;
        float x = sm[c * V_N + v];
        H[base + i] = x;
        __nv_bfloat16 hh, ll;
        split1(x, hh, ll);
        Hh[base + i] = hh;
        Hl[base + i] = ll;
    }
}

/* ------------------------------------------------------------------ */
/* Host driver                                                         */
/* ------------------------------------------------------------------ */
extern "C" void kernel_launch(void* const* d_in, const int* in_sizes, int n_in,
                              void* d_out, int out_size)
{
    const float* in0    = (const float*)d_in[0];
    const float* in1    = (const float*)d_in[1];
    const float* in2    = (const float*)d_in[2];
    const float* hidden = (const float*)d_in[3];
    const float* A      = (const float*)d_in[4];
    const float* emul   = (const float*)d_in[5];
    const float* eadd   = (const float*)d_in[6];
    const float* conv_w = (const float*)d_in[7];
    const float* conv_b = (const float*)d_in[8];
    const float* Wir    = (const float*)d_in[9];
    const float* bir    = (const float*)d_in[10];
    const float* Wii    = (const float*)d_in[11];
    const float* bii    = (const float*)d_in[12];
    const float* Win    = (const float*)d_in[13];
    const float* b_in   = (const float*)d_in[14];
    const float* Whr    = (const float*)d_in[15];
    const float* Whi    = (const float*)d_in[16];
    const float* Whh    = (const float*)d_in[17];
    const float* W1     = (const float*)d_in[18];
    const float* b1     = (const float*)d_in[19];
    const float* W2     = (const float*)d_in[20];
    const float* b2     = (const float*)d_in[21];
    const float* W3     = (const float*)d_in[22];
    const float* b3     = (const float*)d_in[23];
    float* out = (float*)d_out;

    float *pHA, *pHB, *pY, *pG, *pPbase, *pPart;
    cudaGetSymbolAddress((void**)&pHA, g_HA);
    cudaGetSymbolAddress((void**)&pHB, g_HB);
    cudaGetSymbolAddress((void**)&pY,  g_Y);
    cudaGetSymbolAddress((void**)&pG,  g_G);
    cudaGetSymbolAddress((void**)&pPbase, g_P);
    cudaGetSymbolAddress((void**)&pPart,  g_part);

    __nv_bfloat16 *pHAh, *pHAl, *pHBh, *pHBl, *pMh, *pMl, *pD1h, *pD1l;
    __nv_bfloat16 *pcwH, *pcwL, *pWhH, *pWhL, *pW1H, *pW1L, *pW2H, *pW2L;
    cudaGetSymbolAddress((void**)&pHAh, g_HAh);
    cudaGetSymbolAddress((void**)&pHAl, g_HAl);
    cudaGetSymbolAddress((void**)&pHBh, g_HBh);
    cudaGetSymbolAddress((void**)&pHBl, g_HBl);
    cudaGetSymbolAddress((void**)&pMh,  g_Mh);
    cudaGetSymbolAddress((void**)&pMl,  g_Ml);
    cudaGetSymbolAddress((void**)&pD1h, g_D1h);
    cudaGetSymbolAddress((void**)&pD1l, g_D1l);
    cudaGetSymbolAddress((void**)&pcwH, g_cwH);
    cudaGetSymbolAddress((void**)&pcwL, g_cwL);
    cudaGetSymbolAddress((void**)&pWhH, g_WhH);
    cudaGetSymbolAddress((void**)&pWhL, g_WhL);
    cudaGetSymbolAddress((void**)&pW1H, g_W1H);
    cudaGetSymbolAddress((void**)&pW1L, g_W1L);
    cudaGetSymbolAddress((void**)&pW2H, g_W2H);
    cudaGetSymbolAddress((void**)&pW2L, g_W2L);

    float* Pbuf[4];
    for (int i = 0; i < 4; i++) Pbuf[i] = pPbase + (size_t)i * NV * 3;

    cudaFuncSetAttribute(gemm_mma,
                         cudaFuncAttributeMaxDynamicSharedMemorySize, GEMM_SMEM);

    /* per-launch prep */
    prep_aadj<<<(K_N * V_N * 28 + 255) / 256, 256>>>(A, emul, eadd);
    transpose_h<<<N_BATCH, 256>>>(hidden, pHA, pHAh, pHAl);
    split_weights<<<524288 / 256, 256>>>(conv_w, Whr, Whi, Whh, W1, W2);
    cudaMemcpyAsync(Pbuf[0], in0, (size_t)NV * 3 * sizeof(float),
                    cudaMemcpyDeviceToDevice, 0);
    cudaMemcpyAsync(Pbuf[1], in1, (size_t)NV * 3 * sizeof(float),
                    cudaMemcpyDeviceToDevice, 0);
    cudaMemcpyAsync(Pbuf[2], in2, (size_t)NV * 3 * sizeof(float),
                    cudaMemcpyDeviceToDevice, 0);

    const dim3 grid768(6, NV / 128);
    const dim3 grid256(2, NV / 128);

    for (int s = 0; s < TS; s++) {
        float* Hcur  = (s & 1) ? pHB : pHA;
        float* Hnext = (s & 1) ? pHA : pHB;
        const __nv_bfloat16* Hch = (s & 1) ? pHBh : pHAh;
        const __nv_bfloat16* Hcl = (s & 1) ? pHBl : pHAl;
        __nv_bfloat16* Hnh = (s & 1) ? pHAh : pHBh;
        __nv_bfloat16* Hnl = (s & 1) ? pHAl : pHBl;

        const __nv_bfloat16 *GAh = Hch, *GAl = Hcl;
        if (s < 10) {
            gemm_mma<<<grid768, 256, GEMM_SMEM>>>(Hch, Hcl, pcwH, pcwL,
                                                  pY, nullptr, nullptr,
                                                  768, conv_b, 1, nullptr, nullptr);
            graphmix_kernel<<<N_BATCH, 256>>>(pY, pMh, pMl);
            GAh = pMh;
            GAl = pMl;
        }

        gemm_mma<<<grid768, 256, GEMM_SMEM>>>(GAh, GAl, pWhH, pWhL,
                                              pG, nullptr, nullptr,
                                              768, nullptr, 0, nullptr, nullptr);

        int m4 = s & 3;
        int i1   = (4 - m4) & 3;
        int i2   = (5 - m4) & 3;
        int i3   = (6 - m4) & 3;
        int inew = (7 - m4) & 3;

        gru_kernel<<<NV, 256>>>(Hcur, pG, Pbuf[i1], Pbuf[i2], Pbuf[i3],
                                Wir, bir, Wii, bii, Win, b_in,
                                Hnext, Hnh, Hnl, s);

        gemm_mma<<<grid256, 256, GEMM_SMEM>>>(Hnh, Hnl, pW1H, pW1L,
                                              nullptr, pD1h, pD1l,
                                              256, b1, 2, nullptr, nullptr);
        /* W2 GEMM with fused W3 projection: emits 3 partials/row */
        gemm_mma<<<grid256, 256, GEMM_SMEM>>>(pD1h, pD1l, pW2H, pW2L,
                                              nullptr, nullptr, nullptr,
                                              256, b2, 3, W3, pPart);

        out_combine<<<NV / 256, 256>>>(pPart, b3, Pbuf[i1], Pbuf[inew], out, s);
    }
}